// round 12
// baseline (speedup 1.0000x reference)
#include <cuda_runtime.h>
#include <cstdint>

#define NSEQ 2048
#define SCALEQ 0.18033688011112042f   // (1/sqrt(64)) * log2(e)

static const size_t ATT_OFF = 2097152;   // 16*2048*64

// smem float offsets
#define QP    0        // Q (prologue+aq) / P tile (pass B): 128 x 68
#define KS0   8704     // pass B K: 64 x 68
#define KS1   13056
#define VS0   17408    // pass B V: 64 x 72
#define VS1   22016
#define KA0   8704     // pass A K: 128 x 68 (aliases KS0/KS1)
#define KA1   17408    //            (aliases VS0/VS1)
#define MSK   26624    // 64 u32
#define SLP   26688    // 4 x 128 partial row sums
#define RRI   27200    // 128
#define SMEMF 27328    // 109,312 B

#define KVELEMS (16 * 2048 * 64)
__device__ float g_kc[KVELEMS];   // K pre-converted to tf32 bits
__device__ float g_vc[KVELEMS];   // V pre-converted to tf32 bits

__device__ __forceinline__ uint32_t smem_u32(const void* p) {
    uint32_t a;
    asm("{ .reg .u64 t; cvta.to.shared.u64 t, %1; cvt.u32.u64 %0, t; }" : "=r"(a) : "l"(p));
    return a;
}
__device__ __forceinline__ float ex2f_(float x) {
    float y; asm("ex2.approx.ftz.f32 %0, %1;" : "=f"(y) : "f"(x)); return y;
}
__device__ __forceinline__ unsigned cvt_tf32(float x) {
    unsigned y; asm("cvt.rna.tf32.f32 %0, %1;" : "=r"(y) : "f"(x)); return y;
}
__device__ __forceinline__ void mma_tf32(float c[4],
                                         unsigned a0, unsigned a1, unsigned a2, unsigned a3,
                                         unsigned b0, unsigned b1) {
    asm volatile(
        "mma.sync.aligned.m16n8k8.row.col.f32.tf32.tf32.f32 "
        "{%0,%1,%2,%3}, {%4,%5,%6,%7}, {%8,%9}, {%0,%1,%2,%3};"
        : "+f"(c[0]), "+f"(c[1]), "+f"(c[2]), "+f"(c[3])
        : "r"(a0), "r"(a1), "r"(a2), "r"(a3), "r"(b0), "r"(b1));
}

__device__ __forceinline__ void cp16(uint32_t dst, const void* src) {
    asm volatile("cp.async.cg.shared.global [%0], [%1], 16;" :: "r"(dst), "l"(src) : "memory");
}
#define CP_COMMIT() asm volatile("cp.async.commit_group;" ::: "memory")
#define CP_WAIT0()  asm volatile("cp.async.wait_group 0;" ::: "memory")
#define BAR_GRP(id) asm volatile("bar.sync %0, 128;" :: "r"(id) : "memory")

// =============== Kernel 0: pre-convert K,V to tf32 bits ===============
__global__ void __launch_bounds__(512, 4)
kv_cvt(const float* __restrict__ k, const float* __restrict__ v) {
    int idx = (blockIdx.x * 512 + threadIdx.x) * 4;   // float4 granule
    if (idx < KVELEMS) {
        float4 tk = *(const float4*)(k + idx);
        float4 tv = *(const float4*)(v + idx);
        uint4 uk, uv;
        uk.x = cvt_tf32(tk.x); uk.y = cvt_tf32(tk.y); uk.z = cvt_tf32(tk.z); uk.w = cvt_tf32(tk.w);
        uv.x = cvt_tf32(tv.x); uv.y = cvt_tf32(tv.y); uv.z = cvt_tf32(tv.z); uv.w = cvt_tf32(tv.w);
        *(uint4*)(g_kc + idx) = uk;
        *(uint4*)(g_vc + idx) = uv;
    }
}

// 64x64 fp32 tile -> smem (512 thr x 2 chunks of 16B)
__device__ __forceinline__ void issue_tile64(uint32_t buf, const float* src, int tid, int strideB) {
#pragma unroll
    for (int it = 0; it < 2; ++it) {
        int idx = tid + it * 512;
        int row = idx >> 4, c16 = (idx & 15) << 4;
        cp16(buf + row * strideB + c16, (const char*)src + row * 256 + c16);
    }
}
// 128x64 fp32 tile -> smem (512 thr x 4 chunks)
__device__ __forceinline__ void issue_tile128(uint32_t buf, const float* src, int tid, int strideB) {
#pragma unroll
    for (int it = 0; it < 4; ++it) {
        int idx = tid + it * 512;
        int row = idx >> 4, c16 = (idx & 15) << 4;
        cp16(buf + row * strideB + c16, (const char*)src + row * 256 + c16);
    }
}

// S warp-tile: rows wm*32..+31, keys keybase + nt*8 (NT n-subtiles); K already tf32 bits
template <int NT>
__device__ __forceinline__ void compute_S_nt(const unsigned aq[8][2][4], const float* __restrict__ Ks,
                                             int keybase, int g, int tig, float c[2][NT][4]) {
#pragma unroll
    for (int ms = 0; ms < 2; ++ms)
#pragma unroll
        for (int nt = 0; nt < NT; ++nt)
#pragma unroll
            for (int e = 0; e < 4; ++e) c[ms][nt][e] = 0.f;
#pragma unroll
    for (int ks = 0; ks < 8; ++ks) {
#pragma unroll
        for (int nt = 0; nt < NT; ++nt) {
            const float* kr = Ks + (keybase + nt * 8 + g) * 68 + ks * 8;
            unsigned b0 = __float_as_uint(kr[tig]);
            unsigned b1 = __float_as_uint(kr[tig + 4]);
            mma_tf32(c[0][nt], aq[ks][0][0], aq[ks][0][1], aq[ks][0][2], aq[ks][0][3], b0, b1);
            mma_tf32(c[1][nt], aq[ks][1][0], aq[ks][1][1], aq[ks][1][2], aq[ks][1][3], b0, b1);
        }
    }
}

__global__ void __launch_bounds__(512, 1)
lg12_kernel(const float* __restrict__ q, const int* __restrict__ mask,
            float* __restrict__ out) {
    extern __shared__ float sm[];
    const uint32_t sbu = smem_u32(sm);
    const int tid = threadIdx.x;
    const int w = tid >> 5, lane = tid & 31;
    const int wm = w & 3, wn = w >> 2;           // 4 row groups x 4 key groups
    const int g = lane >> 2, tig = lane & 3;
    const int gtid = wn * 32 + lane;             // 0..127 within wm-group

    const int bh = blockIdx.y, b = bh >> 2;      // H = 4
    const int i0 = blockIdx.x * 128;
    const float* qg = q + ((size_t)bh * NSEQ + i0) * 64;
    const float* kg = g_kc + (size_t)bh * NSEQ * 64;
    const float* vg = g_vc + (size_t)bh * NSEQ * 64;
    const int* mg = mask + (size_t)b * NSEQ;
    float* attg = out + ATT_OFF + ((size_t)bh * NSEQ + i0) * NSEQ;
    const unsigned* mw = (const unsigned*)(sm + MSK);

    // ---- prologue: Q (scaled, tf32) into QP; mask bitwords; K mega-tile 0 ----
#pragma unroll
    for (int it = 0; it < 4; ++it) {
        int idx = tid + it * 512;
        int r = idx >> 4, c4 = (idx & 15) << 2;
        float4 t = *(const float4*)(qg + r * 64 + c4);
        uint4 u;
        u.x = cvt_tf32(t.x * SCALEQ); u.y = cvt_tf32(t.y * SCALEQ);
        u.z = cvt_tf32(t.z * SCALEQ); u.w = cvt_tf32(t.w * SCALEQ);
        *(uint4*)(sm + QP + r * 68 + c4) = u;
    }
    if (tid < 64) {
        unsigned bits = 0;
#pragma unroll 8
        for (int r = 0; r < 32; ++r) bits |= (mg[tid * 32 + r] != 0 ? 1u : 0u) << r;
        ((unsigned*)(sm + MSK))[tid] = bits;
    }
    issue_tile128(sbu + KA0 * 4, kg, tid, 272);
    CP_COMMIT();
    __syncthreads();

    // Q A-fragments register-resident for both passes
    unsigned aq[8][2][4];
#pragma unroll
    for (int ks = 0; ks < 8; ++ks)
#pragma unroll
        for (int ms = 0; ms < 2; ++ms) {
            const float* qr = sm + QP + (wm * 32 + ms * 16 + g) * 68 + ks * 8;
            aq[ks][ms][0] = __float_as_uint(qr[tig]);
            aq[ks][ms][1] = __float_as_uint(qr[8 * 68 + tig]);
            aq[ks][ms][2] = __float_as_uint(qr[tig + 4]);
            aq[ks][ms][3] = __float_as_uint(qr[8 * 68 + tig + 4]);
        }

    // =================== Pass A: row sums, 128-key mega-tiles (16 iters) ===================
    float l[4] = {0.f, 0.f, 0.f, 0.f};   // slot s: row wm*32 + (s>>1)*16 + g + (s&1)*8
    for (int j = 0; j < 16; ++j) {
        CP_WAIT0();
        __syncthreads();
        if (j < 15) {
            issue_tile128(sbu + (((j + 1) & 1) ? KA1 : KA0) * 4, kg + (size_t)(j + 1) * 128 * 64, tid, 272);
            CP_COMMIT();
        }
        float c[2][4][4];
        compute_S_nt<4>(aq, sm + ((j & 1) ? KA1 : KA0), wn * 32, g, tig, c);

        unsigned wbits = mw[4 * j + wn];
#pragma unroll
        for (int ms = 0; ms < 2; ++ms)
#pragma unroll
            for (int nt = 0; nt < 4; ++nt) {
                int base = nt * 8 + 2 * tig;
                float e0 = ((wbits >> base) & 1u) ? ex2f_(c[ms][nt][0]) : 0.f;
                float e1 = ((wbits >> (base + 1)) & 1u) ? ex2f_(c[ms][nt][1]) : 0.f;
                float e2 = ((wbits >> base) & 1u) ? ex2f_(c[ms][nt][2]) : 0.f;
                float e3 = ((wbits >> (base + 1)) & 1u) ? ex2f_(c[ms][nt][3]) : 0.f;
                l[ms * 2] += e0 + e1;
                l[ms * 2 + 1] += e2 + e3;
            }
    }

    // KS0 prefetch is safe now (aliases KA0; last pass-A tile used KA1)
    issue_tile64(sbu + KS0 * 4, kg, tid, 272);
    CP_COMMIT();

    // reduce l: tig lanes, then wn groups via smem
#pragma unroll
    for (int s = 0; s < 4; ++s) {
        l[s] += __shfl_xor_sync(0xffffffffu, l[s], 1);
        l[s] += __shfl_xor_sync(0xffffffffu, l[s], 2);
    }
    if (tig == 0) {
#pragma unroll
        for (int s = 0; s < 4; ++s) {
            int row = wm * 32 + (s >> 1) * 16 + g + (s & 1) * 8;
            sm[SLP + wn * 128 + row] = l[s];
        }
    }
    __syncthreads();   // everyone done reading KA1 -> VS0 (aliasing it) now safe
    issue_tile64(sbu + VS0 * 4, vg, tid, 288);
    CP_COMMIT();
    if (tid < 128) {
        float lt = sm[SLP + tid] + sm[SLP + 128 + tid] + sm[SLP + 256 + tid] + sm[SLP + 384 + tid];
        sm[RRI + tid] = 1.0f / lt;
    }
    __syncthreads();

    float rri[4];
#pragma unroll
    for (int s = 0; s < 4; ++s)
        rri[s] = sm[RRI + wm * 32 + (s >> 1) * 16 + g + (s & 1) * 8];

    // =================== Pass B: P, attention, PV (32 iters) ===================
    float o[2][2][4];
#pragma unroll
    for (int ms = 0; ms < 2; ++ms)
#pragma unroll
        for (int nt = 0; nt < 2; ++nt)
#pragma unroll
            for (int e = 0; e < 4; ++e) o[ms][nt][e] = 0.f;

    float* Pm = sm + QP + wm * (32 * 68);   // P staging, wm-group private (stride 68)

    for (int j = 0; j < 32; ++j) {
        CP_WAIT0();
        __syncthreads();   // K/V(j) ready; P(j-1) fully consumed by all groups
        if (j < 31) {
            issue_tile64(sbu + (((j + 1) & 1) ? KS1 : KS0) * 4, kg + (size_t)(j + 1) * 64 * 64, tid, 272);
            issue_tile64(sbu + (((j + 1) & 1) ? VS1 : VS0) * 4, vg + (size_t)(j + 1) * 64 * 64, tid, 288);
            CP_COMMIT();
        }

        float c[2][2][4];
        compute_S_nt<2>(aq, sm + ((j & 1) ? KS1 : KS0), wn * 16, g, tig, c);

        unsigned wbits = mw[2 * j + (wn >> 1)];
#pragma unroll
        for (int ms = 0; ms < 2; ++ms)
#pragma unroll
            for (int nt = 0; nt < 2; ++nt) {
                int base = (wn & 1) * 16 + nt * 8 + 2 * tig;
                float p0 = ((wbits >> base) & 1u) ? ex2f_(c[ms][nt][0]) * rri[2 * ms] : 0.f;
                float p1 = ((wbits >> (base + 1)) & 1u) ? ex2f_(c[ms][nt][1]) * rri[2 * ms] : 0.f;
                float p2 = ((wbits >> base) & 1u) ? ex2f_(c[ms][nt][2]) * rri[2 * ms + 1] : 0.f;
                float p3 = ((wbits >> (base + 1)) & 1u) ? ex2f_(c[ms][nt][3]) * rri[2 * ms + 1] : 0.f;
                int lr = ms * 16 + g, lc = wn * 16 + nt * 8 + 2 * tig;
                *(uint2*)(Pm + lr * 68 + lc) = make_uint2(cvt_tf32(p0), cvt_tf32(p1));
                *(uint2*)(Pm + (lr + 8) * 68 + lc) = make_uint2(cvt_tf32(p2), cvt_tf32(p3));
            }
        BAR_GRP(wm + 1);   // P(j) visible within this wm-group (128 threads)

        // attention store: this wm-group stores its own 32 rows (coalesced 256B segs)
#pragma unroll
        for (int it = 0; it < 4; ++it) {
            int idx = gtid + it * 128;
            int rloc = idx >> 4, c4 = (idx & 15) << 2;
            float4 pv = *(const float4*)(sm + QP + (wm * 32 + rloc) * 68 + c4);
            *(float4*)(attg + (size_t)(wm * 32 + rloc) * NSEQ + j * 64 + c4) = pv;
        }

        // PV: this warp, all 64 keys x its 16 d-columns (P and V already tf32 bits)
        const float* Vs = sm + ((j & 1) ? VS1 : VS0);
#pragma unroll
        for (int kb = 0; kb < 8; ++kb) {
            unsigned a[2][4];
#pragma unroll
            for (int ms = 0; ms < 2; ++ms) {
                const float* pr = Pm + (ms * 16 + g) * 68 + kb * 8;
                a[ms][0] = __float_as_uint(pr[tig]);
                a[ms][1] = __float_as_uint(pr[8 * 68 + tig]);
                a[ms][2] = __float_as_uint(pr[tig + 4]);
                a[ms][3] = __float_as_uint(pr[8 * 68 + tig + 4]);
            }
#pragma unroll
            for (int nt = 0; nt < 2; ++nt) {
                unsigned b0 = __float_as_uint(Vs[(kb * 8 + tig) * 72 + wn * 16 + nt * 8 + g]);
                unsigned b1 = __float_as_uint(Vs[(kb * 8 + tig + 4) * 72 + wn * 16 + nt * 8 + g]);
                mma_tf32(o[0][nt], a[0][0], a[0][1], a[0][2], a[0][3], b0, b1);
                mma_tf32(o[1][nt], a[1][0], a[1][1], a[1][2], a[1][3], b0, b1);
            }
        }
    }

    // ---- O store (already normalized) ----
#pragma unroll
    for (int ms = 0; ms < 2; ++ms)
#pragma unroll
        for (int nt = 0; nt < 2; ++nt) {
            int row = wm * 32 + ms * 16 + g;
            int col = wn * 16 + nt * 8 + 2 * tig;
            float* og0 = out + ((size_t)bh * NSEQ + i0 + row) * 64 + col;
            float* og1 = out + ((size_t)bh * NSEQ + i0 + row + 8) * 64 + col;
            *(float2*)og0 = make_float2(o[ms][nt][0], o[ms][nt][1]);
            *(float2*)og1 = make_float2(o[ms][nt][2], o[ms][nt][3]);
        }
}

extern "C" void kernel_launch(void* const* d_in, const int* in_sizes, int n_in,
                              void* d_out, int out_size) {
    const float* q = (const float*)d_in[0];
    const float* k = (const float*)d_in[1];
    const float* v = (const float*)d_in[2];
    const int* mask = (const int*)d_in[3];
    float* out = (float*)d_out;

    const int smem_bytes = SMEMF * (int)sizeof(float);   // 109,312 B
    cudaFuncSetAttribute(lg12_kernel, cudaFuncAttributeMaxDynamicSharedMemorySize, smem_bytes);

    kv_cvt<<<KVELEMS / (512 * 4), 512>>>(k, v);
    dim3 grid(NSEQ / 128, 16);
    lg12_kernel<<<grid, 512, smem_bytes>>>(q, mask, out);
}

// round 13
// speedup vs baseline: 1.0517x; 1.0517x over previous
#include <cuda_runtime.h>
#include <cstdint>

#define NSEQ 2048
#define SCALEQ 0.18033688011112042f   // (1/sqrt(64)) * log2(e)

static const size_t ATT_OFF = 2097152;   // 16*2048*64

// smem float offsets
#define QP    0        // Q staging / P buffer 0: 128 x 68
#define P1B   8704     // P buffer 1: 128 x 68
#define KS0   17408    // pass B K: 64 x 68
#define KS1   21760
#define VS0   26112    // pass B V ring: 3 x (64 x 72)
#define KA0   17408    // pass A K mega: 128 x 68 (= KS0+KS1)
#define KA1   26112    // pass A K mega (inside V ring region)
#define MSK   39936    // 64 u32
#define SLP   40000    // 4 x 128 partial row sums
#define RRI   40512    // 128
#define SMEMF 40640    // 162,560 B

#define KVELEMS (16 * 2048 * 64)
__device__ float g_kc[KVELEMS];   // K pre-converted to tf32 bits
__device__ float g_vc[KVELEMS];   // V pre-converted to tf32 bits

__device__ __forceinline__ uint32_t smem_u32(const void* p) {
    uint32_t a;
    asm("{ .reg .u64 t; cvta.to.shared.u64 t, %1; cvt.u32.u64 %0, t; }" : "=r"(a) : "l"(p));
    return a;
}
__device__ __forceinline__ float ex2f_(float x) {
    float y; asm("ex2.approx.ftz.f32 %0, %1;" : "=f"(y) : "f"(x)); return y;
}
__device__ __forceinline__ unsigned cvt_tf32(float x) {
    unsigned y; asm("cvt.rna.tf32.f32 %0, %1;" : "=r"(y) : "f"(x)); return y;
}
__device__ __forceinline__ void mma_tf32(float c[4],
                                         unsigned a0, unsigned a1, unsigned a2, unsigned a3,
                                         unsigned b0, unsigned b1) {
    asm volatile(
        "mma.sync.aligned.m16n8k8.row.col.f32.tf32.tf32.f32 "
        "{%0,%1,%2,%3}, {%4,%5,%6,%7}, {%8,%9}, {%0,%1,%2,%3};"
        : "+f"(c[0]), "+f"(c[1]), "+f"(c[2]), "+f"(c[3])
        : "r"(a0), "r"(a1), "r"(a2), "r"(a3), "r"(b0), "r"(b1));
}

__device__ __forceinline__ void cp16(uint32_t dst, const void* src) {
    asm volatile("cp.async.cg.shared.global [%0], [%1], 16;" :: "r"(dst), "l"(src) : "memory");
}
#define CP_COMMIT() asm volatile("cp.async.commit_group;" ::: "memory")
#define CP_WAIT0()  asm volatile("cp.async.wait_group 0;" ::: "memory")

// =============== Kernel 0: pre-convert K,V to tf32 bits ===============
__global__ void __launch_bounds__(512, 4)
kv_cvt(const float* __restrict__ k, const float* __restrict__ v) {
    int idx = (blockIdx.x * 512 + threadIdx.x) * 4;
    if (idx < KVELEMS) {
        float4 tk = *(const float4*)(k + idx);
        float4 tv = *(const float4*)(v + idx);
        uint4 uk, uv;
        uk.x = cvt_tf32(tk.x); uk.y = cvt_tf32(tk.y); uk.z = cvt_tf32(tk.z); uk.w = cvt_tf32(tk.w);
        uv.x = cvt_tf32(tv.x); uv.y = cvt_tf32(tv.y); uv.z = cvt_tf32(tv.z); uv.w = cvt_tf32(tv.w);
        *(uint4*)(g_kc + idx) = uk;
        *(uint4*)(g_vc + idx) = uv;
    }
}

// 64x64 fp32 tile -> smem (512 thr x 2 chunks of 16B)
__device__ __forceinline__ void issue_tile64(uint32_t buf, const float* src, int tid, int strideB) {
#pragma unroll
    for (int it = 0; it < 2; ++it) {
        int idx = tid + it * 512;
        int row = idx >> 4, c16 = (idx & 15) << 4;
        cp16(buf + row * strideB + c16, (const char*)src + row * 256 + c16);
    }
}
// 128x64 fp32 tile -> smem (512 thr x 4 chunks)
__device__ __forceinline__ void issue_tile128(uint32_t buf, const float* src, int tid, int strideB) {
#pragma unroll
    for (int it = 0; it < 4; ++it) {
        int idx = tid + it * 512;
        int row = idx >> 4, c16 = (idx & 15) << 4;
        cp16(buf + row * strideB + c16, (const char*)src + row * 256 + c16);
    }
}

// S warp-tile: rows wm*32..+31, keys keybase + nt*8 (NT n-subtiles); K already tf32 bits
template <int NT>
__device__ __forceinline__ void compute_S_nt(const unsigned aq[8][2][4], const float* __restrict__ Ks,
                                             int keybase, int g, int tig, float c[2][NT][4]) {
#pragma unroll
    for (int ms = 0; ms < 2; ++ms)
#pragma unroll
        for (int nt = 0; nt < NT; ++nt)
#pragma unroll
            for (int e = 0; e < 4; ++e) c[ms][nt][e] = 0.f;
#pragma unroll
    for (int ks = 0; ks < 8; ++ks) {
#pragma unroll
        for (int nt = 0; nt < NT; ++nt) {
            const float* kr = Ks + (keybase + nt * 8 + g) * 68 + ks * 8;
            unsigned b0 = __float_as_uint(kr[tig]);
            unsigned b1 = __float_as_uint(kr[tig + 4]);
            mma_tf32(c[0][nt], aq[ks][0][0], aq[ks][0][1], aq[ks][0][2], aq[ks][0][3], b0, b1);
            mma_tf32(c[1][nt], aq[ks][1][0], aq[ks][1][1], aq[ks][1][2], aq[ks][1][3], b0, b1);
        }
    }
}

__global__ void __launch_bounds__(512, 1)
lg13_kernel(const float* __restrict__ q, const int* __restrict__ mask,
            float* __restrict__ out) {
    extern __shared__ float sm[];
    const uint32_t sbu = smem_u32(sm);
    const int tid = threadIdx.x;
    const int w = tid >> 5, lane = tid & 31;
    const int wm = w & 3, wn = w >> 2;           // 4 row groups x 4 key groups
    const int g = lane >> 2, tig = lane & 3;

    const int bh = blockIdx.y, b = bh >> 2;      // H = 4
    const int i0 = blockIdx.x * 128;
    const float* qg = q + ((size_t)bh * NSEQ + i0) * 64;
    const float* kg = g_kc + (size_t)bh * NSEQ * 64;
    const float* vg = g_vc + (size_t)bh * NSEQ * 64;
    const int* mg = mask + (size_t)b * NSEQ;
    float* attg = out + ATT_OFF + ((size_t)bh * NSEQ + i0) * NSEQ;
    const unsigned* mw = (const unsigned*)(sm + MSK);

    // ---- prologue: Q (scaled, tf32) into QP; mask bitwords; K mega-tile 0 ----
#pragma unroll
    for (int it = 0; it < 4; ++it) {
        int idx = tid + it * 512;
        int r = idx >> 4, c4 = (idx & 15) << 2;
        float4 t = *(const float4*)(qg + r * 64 + c4);
        uint4 u;
        u.x = cvt_tf32(t.x * SCALEQ); u.y = cvt_tf32(t.y * SCALEQ);
        u.z = cvt_tf32(t.z * SCALEQ); u.w = cvt_tf32(t.w * SCALEQ);
        *(uint4*)(sm + QP + r * 68 + c4) = u;
    }
    if (tid < 64) {
        unsigned bits = 0;
#pragma unroll 8
        for (int r = 0; r < 32; ++r) bits |= (mg[tid * 32 + r] != 0 ? 1u : 0u) << r;
        ((unsigned*)(sm + MSK))[tid] = bits;
    }
    issue_tile128(sbu + KA0 * 4, kg, tid, 272);
    CP_COMMIT();
    __syncthreads();

    // Q A-fragments register-resident for both passes
    unsigned aq[8][2][4];
#pragma unroll
    for (int ks = 0; ks < 8; ++ks)
#pragma unroll
        for (int ms = 0; ms < 2; ++ms) {
            const float* qr = sm + QP + (wm * 32 + ms * 16 + g) * 68 + ks * 8;
            aq[ks][ms][0] = __float_as_uint(qr[tig]);
            aq[ks][ms][1] = __float_as_uint(qr[8 * 68 + tig]);
            aq[ks][ms][2] = __float_as_uint(qr[tig + 4]);
            aq[ks][ms][3] = __float_as_uint(qr[8 * 68 + tig + 4]);
        }

    // =================== Pass A: row sums, 128-key mega-tiles (16 iters) ===================
    float l[4] = {0.f, 0.f, 0.f, 0.f};   // slot s: row wm*32 + (s>>1)*16 + g + (s&1)*8
    for (int j = 0; j < 16; ++j) {
        CP_WAIT0();
        __syncthreads();
        if (j < 15) {
            issue_tile128(sbu + (((j + 1) & 1) ? KA1 : KA0) * 4, kg + (size_t)(j + 1) * 128 * 64, tid, 272);
            CP_COMMIT();
        }
        float c[2][4][4];
        compute_S_nt<4>(aq, sm + ((j & 1) ? KA1 : KA0), wn * 32, g, tig, c);

        unsigned wbits = mw[4 * j + wn];
#pragma unroll
        for (int ms = 0; ms < 2; ++ms)
#pragma unroll
            for (int nt = 0; nt < 4; ++nt) {
                int base = nt * 8 + 2 * tig;
                float e0 = ((wbits >> base) & 1u) ? ex2f_(c[ms][nt][0]) : 0.f;
                float e1 = ((wbits >> (base + 1)) & 1u) ? ex2f_(c[ms][nt][1]) : 0.f;
                float e2 = ((wbits >> base) & 1u) ? ex2f_(c[ms][nt][2]) : 0.f;
                float e3 = ((wbits >> (base + 1)) & 1u) ? ex2f_(c[ms][nt][3]) : 0.f;
                l[ms * 2] += e0 + e1;
                l[ms * 2 + 1] += e2 + e3;
            }
    }

    // K(0) prefetch safe now (KS0+KS1 alias KA0; last mega-iter read KA1)
    issue_tile64(sbu + KS0 * 4, kg, tid, 272);
    CP_COMMIT();

    // reduce l: tig lanes, then wn groups via smem
#pragma unroll
    for (int s = 0; s < 4; ++s) {
        l[s] += __shfl_xor_sync(0xffffffffu, l[s], 1);
        l[s] += __shfl_xor_sync(0xffffffffu, l[s], 2);
    }
    if (tig == 0) {
#pragma unroll
        for (int s = 0; s < 4; ++s) {
            int row = wm * 32 + (s >> 1) * 16 + g + (s & 1) * 8;
            sm[SLP + wn * 128 + row] = l[s];
        }
    }
    __syncthreads();   // all KA1 reads done -> V ring (aliasing it) now writable
    issue_tile64(sbu + VS0 * 4, vg, tid, 288);
    CP_COMMIT();
    if (tid < 128) {
        float lt = sm[SLP + tid] + sm[SLP + 128 + tid] + sm[SLP + 256 + tid] + sm[SLP + 384 + tid];
        sm[RRI + tid] = 1.0f / lt;
    }
    __syncthreads();

    float rri[4];
#pragma unroll
    for (int s = 0; s < 4; ++s)
        rri[s] = sm[RRI + wm * 32 + (s >> 1) * 16 + g + (s & 1) * 8];

    // =================== Pass B: pipelined — iter j consumes P(j-1), produces P(j) ===================
    float o[2][2][4];
#pragma unroll
    for (int ms = 0; ms < 2; ++ms)
#pragma unroll
        for (int nt = 0; nt < 2; ++nt)
#pragma unroll
            for (int e = 0; e < 4; ++e) o[ms][nt][e] = 0.f;

    // helper lambda-ish macros via code blocks; P buffers: buf0 = QP, buf1 = P1B
#define PBUF(jj) (sm + (((jj) & 1) ? P1B : QP))
#define VBUF(jj) (sm + VS0 + ((jj) % 3) * 4608)

    // ---- prologue iteration (j = 0): S(0), softmax, stage P(0) ----
    {
        CP_WAIT0();
        __syncthreads();   // K(0), V(0) arrived
        issue_tile64(sbu + KS1 * 4, kg + (size_t)64 * 64, tid, 272);
        issue_tile64(sbu + (VS0 + 4608) * 4, vg + (size_t)64 * 64, tid, 288);
        CP_COMMIT();

        float c[2][2][4];
        compute_S_nt<2>(aq, sm + KS0, wn * 16, g, tig, c);
        unsigned wbits = mw[wn >> 1];
        float* Pb = PBUF(0);
#pragma unroll
        for (int ms = 0; ms < 2; ++ms)
#pragma unroll
            for (int nt = 0; nt < 2; ++nt) {
                int base = (wn & 1) * 16 + nt * 8 + 2 * tig;
                float p0 = ((wbits >> base) & 1u) ? ex2f_(c[ms][nt][0]) * rri[2 * ms] : 0.f;
                float p1 = ((wbits >> (base + 1)) & 1u) ? ex2f_(c[ms][nt][1]) * rri[2 * ms] : 0.f;
                float p2 = ((wbits >> base) & 1u) ? ex2f_(c[ms][nt][2]) * rri[2 * ms + 1] : 0.f;
                float p3 = ((wbits >> (base + 1)) & 1u) ? ex2f_(c[ms][nt][3]) * rri[2 * ms + 1] : 0.f;
                int lr = wm * 32 + ms * 16 + g, lc = wn * 16 + nt * 8 + 2 * tig;
                *(uint2*)(Pb + lr * 68 + lc) = make_uint2(cvt_tf32(p0), cvt_tf32(p1));
                *(uint2*)(Pb + (lr + 8) * 68 + lc) = make_uint2(cvt_tf32(p2), cvt_tf32(p3));
            }
    }

    // ---- main loop: j = 1..31 ----
    for (int j = 1; j < 32; ++j) {
        CP_WAIT0();
        __syncthreads();   // K/V(j) arrived; P(j-1) visible; P buf (j&1) free

        if (j < 31) {
            issue_tile64(sbu + (((j + 1) & 1) ? KS1 : KS0) * 4, kg + (size_t)(j + 1) * 64 * 64, tid, 272);
            issue_tile64(sbu + (VS0 + ((j + 1) % 3) * 4608) * 4, vg + (size_t)(j + 1) * 64 * 64, tid, 288);
            CP_COMMIT();
        }

        const float* Pp = PBUF(j - 1);

        // attention store for tile j-1 (coalesced 256B row segments)
#pragma unroll
        for (int it = 0; it < 4; ++it) {
            int idx = tid + it * 512;
            int row = idx >> 4, c4 = (idx & 15) << 2;
            float4 pv = *(const float4*)(Pp + row * 68 + c4);
            *(float4*)(attg + (size_t)row * NSEQ + (j - 1) * 64 + c4) = pv;
        }

        // PV(j-1): this warp, all 64 keys x its 16 d-columns
        {
            const float* Vs = VBUF(j - 1);
#pragma unroll
            for (int kb = 0; kb < 8; ++kb) {
                unsigned a[2][4];
#pragma unroll
                for (int ms = 0; ms < 2; ++ms) {
                    const float* pr = Pp + (wm * 32 + ms * 16 + g) * 68 + kb * 8;
                    a[ms][0] = __float_as_uint(pr[tig]);
                    a[ms][1] = __float_as_uint(pr[8 * 68 + tig]);
                    a[ms][2] = __float_as_uint(pr[tig + 4]);
                    a[ms][3] = __float_as_uint(pr[8 * 68 + tig + 4]);
                }
#pragma unroll
                for (int nt = 0; nt < 2; ++nt) {
                    unsigned b0 = __float_as_uint(Vs[(kb * 8 + tig) * 72 + wn * 16 + nt * 8 + g]);
                    unsigned b1 = __float_as_uint(Vs[(kb * 8 + tig + 4) * 72 + wn * 16 + nt * 8 + g]);
                    mma_tf32(o[0][nt], a[0][0], a[0][1], a[0][2], a[0][3], b0, b1);
                    mma_tf32(o[1][nt], a[1][0], a[1][1], a[1][2], a[1][3], b0, b1);
                }
            }
        }

        // S(j) + softmax + stage P(j)
        {
            float c[2][2][4];
            compute_S_nt<2>(aq, sm + ((j & 1) ? KS1 : KS0), wn * 16, g, tig, c);
            unsigned wbits = mw[2 * j + (wn >> 1)];
            float* Pb = PBUF(j);
#pragma unroll
            for (int ms = 0; ms < 2; ++ms)
#pragma unroll
                for (int nt = 0; nt < 2; ++nt) {
                    int base = (wn & 1) * 16 + nt * 8 + 2 * tig;
                    float p0 = ((wbits >> base) & 1u) ? ex2f_(c[ms][nt][0]) * rri[2 * ms] : 0.f;
                    float p1 = ((wbits >> (base + 1)) & 1u) ? ex2f_(c[ms][nt][1]) * rri[2 * ms] : 0.f;
                    float p2 = ((wbits >> base) & 1u) ? ex2f_(c[ms][nt][2]) * rri[2 * ms + 1] : 0.f;
                    float p3 = ((wbits >> (base + 1)) & 1u) ? ex2f_(c[ms][nt][3]) * rri[2 * ms + 1] : 0.f;
                    int lr = wm * 32 + ms * 16 + g, lc = wn * 16 + nt * 8 + 2 * tig;
                    *(uint2*)(Pb + lr * 68 + lc) = make_uint2(cvt_tf32(p0), cvt_tf32(p1));
                    *(uint2*)(Pb + (lr + 8) * 68 + lc) = make_uint2(cvt_tf32(p2), cvt_tf32(p3));
                }
        }
    }

    // ---- epilogue: consume P(31) ----
    __syncthreads();
    {
        const float* Pp = PBUF(31);
#pragma unroll
        for (int it = 0; it < 4; ++it) {
            int idx = tid + it * 512;
            int row = idx >> 4, c4 = (idx & 15) << 2;
            float4 pv = *(const float4*)(Pp + row * 68 + c4);
            *(float4*)(attg + (size_t)row * NSEQ + 31 * 64 + c4) = pv;
        }
        const float* Vs = VBUF(31);
#pragma unroll
        for (int kb = 0; kb < 8; ++kb) {
            unsigned a[2][4];
#pragma unroll
            for (int ms = 0; ms < 2; ++ms) {
                const float* pr = Pp + (wm * 32 + ms * 16 + g) * 68 + kb * 8;
                a[ms][0] = __float_as_uint(pr[tig]);
                a[ms][1] = __float_as_uint(pr[8 * 68 + tig]);
                a[ms][2] = __float_as_uint(pr[tig + 4]);
                a[ms][3] = __float_as_uint(pr[8 * 68 + tig + 4]);
            }
#pragma unroll
            for (int nt = 0; nt < 2; ++nt) {
                unsigned b0 = __float_as_uint(Vs[(kb * 8 + tig) * 72 + wn * 16 + nt * 8 + g]);
                unsigned b1 = __float_as_uint(Vs[(kb * 8 + tig + 4) * 72 + wn * 16 + nt * 8 + g]);
                mma_tf32(o[0][nt], a[0][0], a[0][1], a[0][2], a[0][3], b0, b1);
                mma_tf32(o[1][nt], a[1][0], a[1][1], a[1][2], a[1][3], b0, b1);
            }
        }
    }

    // ---- O store (already normalized) ----
#pragma unroll
    for (int ms = 0; ms < 2; ++ms)
#pragma unroll
        for (int nt = 0; nt < 2; ++nt) {
            int row = wm * 32 + ms * 16 + g;
            int col = wn * 16 + nt * 8 + 2 * tig;
            float* og0 = out + ((size_t)bh * NSEQ + i0 + row) * 64 + col;
            float* og1 = out + ((size_t)bh * NSEQ + i0 + row + 8) * 64 + col;
            *(float2*)og0 = make_float2(o[ms][nt][0], o[ms][nt][1]);
            *(float2*)og1 = make_float2(o[ms][nt][2], o[ms][nt][3]);
        }
#undef PBUF
#undef VBUF
}

extern "C" void kernel_launch(void* const* d_in, const int* in_sizes, int n_in,
                              void* d_out, int out_size) {
    const float* q = (const float*)d_in[0];
    const float* k = (const float*)d_in[1];
    const float* v = (const float*)d_in[2];
    const int* mask = (const int*)d_in[3];
    float* out = (float*)d_out;

    const int smem_bytes = SMEMF * (int)sizeof(float);   // 162,560 B
    cudaFuncSetAttribute(lg13_kernel, cudaFuncAttributeMaxDynamicSharedMemorySize, smem_bytes);

    kv_cvt<<<KVELEMS / (512 * 4), 512>>>(k, v);
    dim3 grid(NSEQ / 128, 16);
    lg13_kernel<<<grid, 512, smem_bytes>>>(q, mask, out);
}